// round 9
// baseline (speedup 1.0000x reference)
#include <cuda_runtime.h>
#include <cstdint>

#define OUT_F 28672
#define IN_F  8192
#define ROW_BYTES 16384            // int32-widened qweight row: 4096 * 4 B
#define RPB 32                     // rows per block
#define CHUNK_B 512                // bytes per row per stage
#define NCHUNK (ROW_BYTES / CHUNK_B)   // 32
#define NSTAGE 4
#define STAGE_B (RPB * CHUNK_B)        // 16 KB per stage
#define NTHREADS 288               // 8 consumer warps + 1 producer warp

// qweight is int32 (harness-widened uint8): each element is one byte value
// 0..255 = two 4-bit codes (lo nibble -> even column, hi nibble -> odd).
//
// Warp-specialized pipeline, no block-wide syncs in the mainloop:
//   - producer warp (w==8): lane r owns row r; per chunk issues one 512 B
//     cp.async.bulk for its row. Runs up to 4 stages ahead of consumers.
//   - consumer warps 0..7: 4 rows each; wait full[s], consume 512 B/row from
//     smem (conflict-free LDS.128), one elect-lane arrives on empty[s].
// full[s]: tx-completed by TMA (init count 1, expect_tx by producer lane 0).
// empty[s]: init count 8 (one arrival per consumer warp).

__device__ __forceinline__ uint32_t smem_u32(const void* p) {
    return (uint32_t)__cvta_generic_to_shared(p);
}
__device__ __forceinline__ void mbar_init(uint32_t mbar, uint32_t count) {
    asm volatile("mbarrier.init.shared.b64 [%0], %1;" :: "r"(mbar), "r"(count) : "memory");
}
__device__ __forceinline__ void mbar_expect_tx(uint32_t mbar, uint32_t bytes) {
    asm volatile("mbarrier.arrive.expect_tx.shared.b64 _, [%0], %1;"
                 :: "r"(mbar), "r"(bytes) : "memory");
}
__device__ __forceinline__ void mbar_arrive(uint32_t mbar) {
    asm volatile("mbarrier.arrive.shared.b64 _, [%0];" :: "r"(mbar) : "memory");
}
__device__ __forceinline__ void bulk_g2s(uint32_t dst, const void* src,
                                         uint32_t bytes, uint32_t mbar) {
    asm volatile(
        "cp.async.bulk.shared::cluster.global.mbarrier::complete_tx::bytes "
        "[%0], [%1], %2, [%3];"
        :: "r"(dst), "l"(src), "r"(bytes), "r"(mbar) : "memory");
}
__device__ __forceinline__ void mbar_wait(uint32_t mbar, uint32_t parity) {
    uint32_t done;
    asm volatile(
        "{\n\t.reg .pred p;\n\t"
        "mbarrier.try_wait.parity.acquire.cta.shared::cta.b64 p, [%1], %2;\n\t"
        "selp.b32 %0, 1, 0, p;\n\t}"
        : "=r"(done) : "r"(mbar), "r"(parity) : "memory");
    if (!done) {
        asm volatile(
            "{\n\t.reg .pred P1;\n\t"
            "WL_%=:\n\t"
            "mbarrier.try_wait.parity.acquire.cta.shared::cta.b64 P1, [%0], %1, 0x989680;\n\t"
            "@P1 bra.uni WD_%=;\n\t"
            "bra.uni WL_%=;\n\t"
            "WD_%=:\n\t}"
            :: "r"(mbar), "r"(parity) : "memory");
    }
}

__global__ __launch_bounds__(NTHREADS, 3)
void q3_matvec_kernel(const float* __restrict__ x,
                      const int* __restrict__ qw,
                      const float* __restrict__ kv,
                      const float* __restrict__ bias,
                      float* __restrict__ y)
{
    __shared__ alignas(128) uint8_t s_buf[NSTAGE][STAGE_B];   // 4 x 16 KB ring
    __shared__ float s_lut[RPB * 16];                         // 32 row-LUTs
    __shared__ alignas(8) uint64_t s_full[NSTAGE];
    __shared__ alignas(8) uint64_t s_empty[NSTAGE];

    const int t = threadIdx.x;
    const int w = t >> 5;
    const int l = t & 31;
    const int rbase = blockIdx.x * RPB;

    // Stage 512 LUT floats with the first 256 threads.
    if (t < 256) {
        s_lut[t]       = kv[rbase * 16 + t];
        s_lut[t + 256] = kv[rbase * 16 + t + 256];
    }
    if (t == 0) {
        #pragma unroll
        for (int s = 0; s < NSTAGE; s++) {
            mbar_init(smem_u32(&s_full[s]), 1);
            mbar_init(smem_u32(&s_empty[s]), 8);
        }
    }
    __syncthreads();

    if (w == 8) {
        // ---- Producer warp: lane l owns row l. ----
        const char* rowp = (const char*)qw + (size_t)(rbase + l) * ROW_BYTES;
        #pragma unroll 1
        for (int c = 0; c < NCHUNK; c++) {
            const int s = c & (NSTAGE - 1);
            const uint32_t fullb  = smem_u32(&s_full[s]);
            const uint32_t emptyb = smem_u32(&s_empty[s]);
            // First pass over the ring must not wait: parity starts flipped.
            mbar_wait(emptyb, 1u ^ ((c >> 2) & 1u));
            if (l == 0) mbar_expect_tx(fullb, STAGE_B);
            __syncwarp();
            bulk_g2s(smem_u32(&s_buf[s][0]) + l * CHUNK_B,
                     rowp + (size_t)c * CHUNK_B, CHUNK_B, fullb);
        }
        return;
    }

    // ---- Consumer warps 0..7: rows 4w..4w+3. ----
    const int wrow = rbase + (w << 2);
    const float* lut0 = s_lut + (w << 2) * 16;
    const float4* xp = reinterpret_cast<const float4*>(x);

    float a00 = 0.f, a01 = 0.f;
    float a10 = 0.f, a11 = 0.f;
    float a20 = 0.f, a21 = 0.f;
    float a30 = 0.f, a31 = 0.f;

    #pragma unroll 1
    for (int c = 0; c < NCHUNK; c++) {
        const int s = c & (NSTAGE - 1);
        mbar_wait(smem_u32(&s_full[s]), (c >> 2) & 1u);

        // Chunk covers columns [c*256, c*256+256): lane l -> cols c*256+8l..+7.
        const float4 xa = xp[(c << 6) + (l << 1)];
        const float4 xb = xp[(c << 6) + (l << 1) + 1];

        const uint8_t* buf = s_buf[s] + ((w << 2) * CHUNK_B) + (l << 4);
        const uint4 q0 = *reinterpret_cast<const uint4*>(buf);
        const uint4 q1 = *reinterpret_cast<const uint4*>(buf + CHUNK_B);
        const uint4 q2 = *reinterpret_cast<const uint4*>(buf + 2 * CHUNK_B);
        const uint4 q3 = *reinterpret_cast<const uint4*>(buf + 3 * CHUNK_B);

        // v <= 255 so (v >> 4) is already a clean code (no mask).
        #define DO_ROW(Q, LUT, A0, A1)                        \
            A0 = fmaf((LUT)[(Q).x & 15u], xa.x, A0);          \
            A1 = fmaf((LUT)[(Q).x >> 4],  xa.y, A1);          \
            A0 = fmaf((LUT)[(Q).y & 15u], xa.z, A0);          \
            A1 = fmaf((LUT)[(Q).y >> 4],  xa.w, A1);          \
            A0 = fmaf((LUT)[(Q).z & 15u], xb.x, A0);          \
            A1 = fmaf((LUT)[(Q).z >> 4],  xb.y, A1);          \
            A0 = fmaf((LUT)[(Q).w & 15u], xb.z, A0);          \
            A1 = fmaf((LUT)[(Q).w >> 4],  xb.w, A1);

        DO_ROW(q0, lut0,      a00, a01)
        DO_ROW(q1, lut0 + 16, a10, a11)
        DO_ROW(q2, lut0 + 32, a20, a21)
        DO_ROW(q3, lut0 + 48, a30, a31)
        #undef DO_ROW

        if (l == 0) mbar_arrive(smem_u32(&s_empty[s]));
    }

    // Four reductions per warp, once.
    float r0 = a00 + a01;
    float r1 = a10 + a11;
    float r2 = a20 + a21;
    float r3 = a30 + a31;
    #pragma unroll
    for (int s = 16; s > 0; s >>= 1) {
        r0 += __shfl_xor_sync(0xffffffffu, r0, s);
        r1 += __shfl_xor_sync(0xffffffffu, r1, s);
        r2 += __shfl_xor_sync(0xffffffffu, r2, s);
        r3 += __shfl_xor_sync(0xffffffffu, r3, s);
    }
    if (l == 0) {
        y[wrow + 0] = r0 + bias[wrow + 0];
        y[wrow + 1] = r1 + bias[wrow + 1];
        y[wrow + 2] = r2 + bias[wrow + 2];
        y[wrow + 3] = r3 + bias[wrow + 3];
    }
}

extern "C" void kernel_launch(void* const* d_in, const int* in_sizes, int n_in,
                              void* d_out, int out_size)
{
    const float* x    = (const float*)d_in[0];
    const int*   qw   = (const int*)d_in[1];
    const float* kv   = (const float*)d_in[2];
    const float* bias = (const float*)d_in[3];
    float*       y    = (float*)d_out;

    dim3 grid(OUT_F / RPB);   // 896 blocks
    dim3 block(NTHREADS);
    q3_matvec_kernel<<<grid, block>>>(x, qw, kv, bias, y);
}

// round 10
// speedup vs baseline: 1.1922x; 1.1922x over previous
#include <cuda_runtime.h>
#include <cstdint>

#define OUT_F 28672
#define IN_F  8192
#define ROW_BYTES 16384            // int32-widened qweight row: 4096 * 4 B
#define RPB 16                     // rows per block
#define CHUNK_B 2048               // bytes per row per stage (one TMA op)
#define NCHUNK (ROW_BYTES / CHUNK_B)   // 8
#define STAGE_B (RPB * CHUNK_B)        // 32 KB per stage

// qweight is int32 (harness-widened uint8): each element is a byte value
// 0..255 = two 4-bit codes (lo nibble -> even column, hi nibble -> odd).
//
// Double-buffered 32 KB stages, cp.async.bulk refill issued by 16 parallel
// threads (one contiguous 2 KB copy per row). 8 sync points per block (vs 16
// in R8): chunk contiguity + fewer convoys were the two proven levers.
// 8 consumer warps x 2 rows each; inner loop identical per 512 B half-chunk.

__device__ __forceinline__ uint32_t smem_u32(const void* p) {
    return (uint32_t)__cvta_generic_to_shared(p);
}
__device__ __forceinline__ void mbar_init(uint32_t mbar, uint32_t count) {
    asm volatile("mbarrier.init.shared.b64 [%0], %1;" :: "r"(mbar), "r"(count) : "memory");
}
__device__ __forceinline__ void mbar_expect_tx(uint32_t mbar, uint32_t bytes) {
    asm volatile("mbarrier.arrive.expect_tx.shared.b64 _, [%0], %1;"
                 :: "r"(mbar), "r"(bytes) : "memory");
}
__device__ __forceinline__ void bulk_g2s(uint32_t dst, const void* src,
                                         uint32_t bytes, uint32_t mbar) {
    asm volatile(
        "cp.async.bulk.shared::cluster.global.mbarrier::complete_tx::bytes "
        "[%0], [%1], %2, [%3];"
        :: "r"(dst), "l"(src), "r"(bytes), "r"(mbar) : "memory");
}
__device__ __forceinline__ void mbar_wait(uint32_t mbar, uint32_t parity) {
    uint32_t done;
    asm volatile(
        "{\n\t.reg .pred p;\n\t"
        "mbarrier.try_wait.parity.acquire.cta.shared::cta.b64 p, [%1], %2;\n\t"
        "selp.b32 %0, 1, 0, p;\n\t}"
        : "=r"(done) : "r"(mbar), "r"(parity) : "memory");
    if (!done) {
        asm volatile(
            "{\n\t.reg .pred P1;\n\t"
            "WL_%=:\n\t"
            "mbarrier.try_wait.parity.acquire.cta.shared::cta.b64 P1, [%0], %1, 0x989680;\n\t"
            "@P1 bra.uni WD_%=;\n\t"
            "bra.uni WL_%=;\n\t"
            "WD_%=:\n\t}"
            :: "r"(mbar), "r"(parity) : "memory");
    }
}

__global__ __launch_bounds__(256, 3)
void q3_matvec_kernel(const float* __restrict__ x,
                      const int* __restrict__ qw,
                      const float* __restrict__ kv,
                      const float* __restrict__ bias,
                      float* __restrict__ y)
{
    __shared__ alignas(128) uint8_t s_buf[2][STAGE_B];   // 2 x 32 KB
    __shared__ float s_lut[RPB * 16];                    // 16 row-LUTs (1 KB)
    __shared__ alignas(8) uint64_t s_mbar[2];

    const int t = threadIdx.x;
    const int w = t >> 5;
    const int l = t & 31;
    const int rbase = blockIdx.x * RPB;
    const int wrow = rbase + (w << 1);      // this warp's 2 rows

    // Stage 256 LUT floats (one per thread).
    s_lut[t] = kv[rbase * 16 + t];

    const uint32_t mb0 = smem_u32(&s_mbar[0]);
    const uint32_t mb1 = smem_u32(&s_mbar[1]);
    const uint32_t bu0 = smem_u32(&s_buf[0][0]);
    const uint32_t bu1 = smem_u32(&s_buf[1][0]);

    if (t == 0) { mbar_init(mb0, 1); mbar_init(mb1, 1); }
    __syncthreads();

    const char* gq = (const char*)qw + (size_t)rbase * ROW_BYTES;

    // Prologue: fill both stages (chunks 0 and 1), 16 parallel issuers.
    if (t == 0) { mbar_expect_tx(mb0, STAGE_B); mbar_expect_tx(mb1, STAGE_B); }
    if (t < RPB) {
        __syncwarp(0x0000ffffu);
        const char* rowp = gq + (size_t)t * ROW_BYTES;
        bulk_g2s(bu0 + t * CHUNK_B, rowp,           CHUNK_B, mb0);
        bulk_g2s(bu1 + t * CHUNK_B, rowp + CHUNK_B, CHUNK_B, mb1);
    }

    const float* lut0 = s_lut + (w << 1) * 16;
    const float4* xp = reinterpret_cast<const float4*>(x);

    float a00 = 0.f, a01 = 0.f;   // row +0
    float a10 = 0.f, a11 = 0.f;   // row +1

    #pragma unroll 1
    for (int c = 0; c < NCHUNK; c++) {
        const int st = c & 1;
        const uint32_t mb = st ? mb1 : mb0;
        mbar_wait(mb, (c >> 1) & 1);

        const uint8_t* wbuf = s_buf[st] + ((w << 1) * CHUNK_B);

        // 4 half-chunks of 512 B per row; chunk covers columns [c*1024, +1024).
        #pragma unroll
        for (int h = 0; h < 4; h++) {
            // x window: columns c*1024 + h*256 + 8l .. +7
            const float4 xa = xp[(c << 8) + (h << 6) + (l << 1)];
            const float4 xb = xp[(c << 8) + (h << 6) + (l << 1) + 1];
            const uint8_t* buf = wbuf + (h << 9) + (l << 4);

            const uint4 q0 = *reinterpret_cast<const uint4*>(buf);
            const uint4 q1 = *reinterpret_cast<const uint4*>(buf + CHUNK_B);

            // v <= 255 so (v >> 4) is already a clean code (no mask).
            #define DO_ROW(Q, LUT, A0, A1)                        \
                A0 = fmaf((LUT)[(Q).x & 15u], xa.x, A0);          \
                A1 = fmaf((LUT)[(Q).x >> 4],  xa.y, A1);          \
                A0 = fmaf((LUT)[(Q).y & 15u], xa.z, A0);          \
                A1 = fmaf((LUT)[(Q).y >> 4],  xa.w, A1);          \
                A0 = fmaf((LUT)[(Q).z & 15u], xb.x, A0);          \
                A1 = fmaf((LUT)[(Q).z >> 4],  xb.y, A1);          \
                A0 = fmaf((LUT)[(Q).w & 15u], xb.z, A0);          \
                A1 = fmaf((LUT)[(Q).w >> 4],  xb.w, A1);

            DO_ROW(q0, lut0,      a00, a01)
            DO_ROW(q1, lut0 + 16, a10, a11)
            #undef DO_ROW
        }

        __syncthreads();   // stage st fully consumed by all warps

        if (c + 2 < NCHUNK) {
            if (t == 0) mbar_expect_tx(mb, STAGE_B);
            if (t < RPB) {
                __syncwarp(0x0000ffffu);
                const uint32_t bu = st ? bu1 : bu0;
                bulk_g2s(bu + t * CHUNK_B,
                         gq + (size_t)t * ROW_BYTES + (size_t)(c + 2) * CHUNK_B,
                         CHUNK_B, mb);
            }
        }
    }

    // Two reductions per warp, once.
    float r0 = a00 + a01;
    float r1 = a10 + a11;
    #pragma unroll
    for (int s = 16; s > 0; s >>= 1) {
        r0 += __shfl_xor_sync(0xffffffffu, r0, s);
        r1 += __shfl_xor_sync(0xffffffffu, r1, s);
    }
    if (l == 0) {
        y[wrow + 0] = r0 + bias[wrow + 0];
        y[wrow + 1] = r1 + bias[wrow + 1];
    }
}

extern "C" void kernel_launch(void* const* d_in, const int* in_sizes, int n_in,
                              void* d_out, int out_size)
{
    const float* x    = (const float*)d_in[0];
    const int*   qw   = (const int*)d_in[1];
    const float* kv   = (const float*)d_in[2];
    const float* bias = (const float*)d_in[3];
    float*       y    = (float*)d_out;

    dim3 grid(OUT_F / RPB);   // 1792 blocks
    dim3 block(256);
    q3_matvec_kernel<<<grid, block>>>(x, qw, kv, bias, y);
}

// round 11
// speedup vs baseline: 1.2802x; 1.0738x over previous
#include <cuda_runtime.h>
#include <cstdint>

#define OUT_F 28672
#define IN_F  8192
#define ROW_BYTES 16384            // int32-widened qweight row: 4096 * 4 B
#define RPB 16                     // rows per block (4 warps x 4 rows)
#define CHUNK_B 1024               // bytes per row per stage
#define NCHUNK (ROW_BYTES / CHUNK_B)   // 16
#define STAGE_B (RPB * CHUNK_B)        // 16 KB per stage

// qweight is int32 (harness-widened uint8): each element is a byte value
// 0..255 = two 4-bit codes (lo nibble -> even column, hi nibble -> odd).
//
// R8 structure (proven best: 1 KB contiguous TMA chunks, parallel refill,
// 4 rows/warp amortization) with a 4-warp block: barrier convoys span 4 warps
// instead of 8, and 6 independent block-pipelines per SM (vs 3) smooth the
// DRAM request stream around sync points. In-flight/SM unchanged (~96 KB).

__device__ __forceinline__ uint32_t smem_u32(const void* p) {
    return (uint32_t)__cvta_generic_to_shared(p);
}
__device__ __forceinline__ void mbar_init(uint32_t mbar, uint32_t count) {
    asm volatile("mbarrier.init.shared.b64 [%0], %1;" :: "r"(mbar), "r"(count) : "memory");
}
__device__ __forceinline__ void mbar_expect_tx(uint32_t mbar, uint32_t bytes) {
    asm volatile("mbarrier.arrive.expect_tx.shared.b64 _, [%0], %1;"
                 :: "r"(mbar), "r"(bytes) : "memory");
}
__device__ __forceinline__ void bulk_g2s(uint32_t dst, const void* src,
                                         uint32_t bytes, uint32_t mbar) {
    asm volatile(
        "cp.async.bulk.shared::cluster.global.mbarrier::complete_tx::bytes "
        "[%0], [%1], %2, [%3];"
        :: "r"(dst), "l"(src), "r"(bytes), "r"(mbar) : "memory");
}
__device__ __forceinline__ void mbar_wait(uint32_t mbar, uint32_t parity) {
    uint32_t done;
    asm volatile(
        "{\n\t.reg .pred p;\n\t"
        "mbarrier.try_wait.parity.acquire.cta.shared::cta.b64 p, [%1], %2;\n\t"
        "selp.b32 %0, 1, 0, p;\n\t}"
        : "=r"(done) : "r"(mbar), "r"(parity) : "memory");
    if (!done) {
        asm volatile(
            "{\n\t.reg .pred P1;\n\t"
            "WL_%=:\n\t"
            "mbarrier.try_wait.parity.acquire.cta.shared::cta.b64 P1, [%0], %1, 0x989680;\n\t"
            "@P1 bra.uni WD_%=;\n\t"
            "bra.uni WL_%=;\n\t"
            "WD_%=:\n\t}"
            :: "r"(mbar), "r"(parity) : "memory");
    }
}

__global__ __launch_bounds__(128, 6)
void q3_matvec_kernel(const float* __restrict__ x,
                      const int* __restrict__ qw,
                      const float* __restrict__ kv,
                      const float* __restrict__ bias,
                      float* __restrict__ y)
{
    __shared__ alignas(128) uint8_t s_buf[2][STAGE_B];   // 2 x 16 KB
    __shared__ float s_lut[RPB * 16];                    // 16 row-LUTs (1 KB)
    __shared__ alignas(8) uint64_t s_mbar[2];

    const int t = threadIdx.x;
    const int w = t >> 5;
    const int l = t & 31;
    const int rbase = blockIdx.x * RPB;
    const int wrow = rbase + (w << 2);      // this warp's 4 rows

    // Stage 256 LUT floats (2 per thread).
    s_lut[t]      = kv[rbase * 16 + t];
    s_lut[t + 128] = kv[rbase * 16 + t + 128];

    const uint32_t mb0 = smem_u32(&s_mbar[0]);
    const uint32_t mb1 = smem_u32(&s_mbar[1]);
    const uint32_t bu0 = smem_u32(&s_buf[0][0]);
    const uint32_t bu1 = smem_u32(&s_buf[1][0]);

    if (t == 0) { mbar_init(mb0, 1); mbar_init(mb1, 1); }
    __syncthreads();

    const char* gq = (const char*)qw + (size_t)rbase * ROW_BYTES;

    // Prologue: fill both stages (chunks 0 and 1), 16 parallel issuers.
    if (t == 0) { mbar_expect_tx(mb0, STAGE_B); mbar_expect_tx(mb1, STAGE_B); }
    if (t < RPB) {
        __syncwarp(0x0000ffffu);
        const char* rowp = gq + (size_t)t * ROW_BYTES;
        bulk_g2s(bu0 + t * CHUNK_B, rowp,           CHUNK_B, mb0);
        bulk_g2s(bu1 + t * CHUNK_B, rowp + CHUNK_B, CHUNK_B, mb1);
    }

    const float* lut0 = s_lut + (w << 2) * 16;
    const float4* xp = reinterpret_cast<const float4*>(x);

    float a00 = 0.f, a01 = 0.f;
    float a10 = 0.f, a11 = 0.f;
    float a20 = 0.f, a21 = 0.f;
    float a30 = 0.f, a31 = 0.f;

    #pragma unroll 1
    for (int c = 0; c < NCHUNK; c++) {
        const int st = c & 1;
        const uint32_t mb = st ? mb1 : mb0;
        mbar_wait(mb, (c >> 1) & 1);

        const uint8_t* wbuf = s_buf[st] + ((w << 2) * CHUNK_B);

        // Two 512 B half-chunks per row; x window per half from L1.
        #pragma unroll
        for (int h = 0; h < 2; h++) {
            const float4 xa = xp[(c << 7) + (h << 6) + (l << 1)];
            const float4 xb = xp[(c << 7) + (h << 6) + (l << 1) + 1];
            const uint8_t* buf = wbuf + (h << 9) + (l << 4);

            const uint4 q0 = *reinterpret_cast<const uint4*>(buf);
            const uint4 q1 = *reinterpret_cast<const uint4*>(buf + CHUNK_B);
            const uint4 q2 = *reinterpret_cast<const uint4*>(buf + 2 * CHUNK_B);
            const uint4 q3 = *reinterpret_cast<const uint4*>(buf + 3 * CHUNK_B);

            // v <= 255 so (v >> 4) is already a clean code (no mask).
            #define DO_ROW(Q, LUT, A0, A1)                        \
                A0 = fmaf((LUT)[(Q).x & 15u], xa.x, A0);          \
                A1 = fmaf((LUT)[(Q).x >> 4],  xa.y, A1);          \
                A0 = fmaf((LUT)[(Q).y & 15u], xa.z, A0);          \
                A1 = fmaf((LUT)[(Q).y >> 4],  xa.w, A1);          \
                A0 = fmaf((LUT)[(Q).z & 15u], xb.x, A0);          \
                A1 = fmaf((LUT)[(Q).z >> 4],  xb.y, A1);          \
                A0 = fmaf((LUT)[(Q).w & 15u], xb.z, A0);          \
                A1 = fmaf((LUT)[(Q).w >> 4],  xb.w, A1);

            DO_ROW(q0, lut0,      a00, a01)
            DO_ROW(q1, lut0 + 16, a10, a11)
            DO_ROW(q2, lut0 + 32, a20, a21)
            DO_ROW(q3, lut0 + 48, a30, a31)
            #undef DO_ROW
        }

        __syncthreads();   // stage st fully consumed (4-warp barrier)

        if (c + 2 < NCHUNK) {
            if (t == 0) mbar_expect_tx(mb, STAGE_B);
            if (t < RPB) {
                __syncwarp(0x0000ffffu);
                const uint32_t bu = st ? bu1 : bu0;
                bulk_g2s(bu + t * CHUNK_B,
                         gq + (size_t)t * ROW_BYTES + (size_t)(c + 2) * CHUNK_B,
                         CHUNK_B, mb);
            }
        }
    }

    // Four reductions per warp, once.
    float r0 = a00 + a01;
    float r1 = a10 + a11;
    float r2 = a20 + a21;
    float r3 = a30 + a31;
    #pragma unroll
    for (int s = 16; s > 0; s >>= 1) {
        r0 += __shfl_xor_sync(0xffffffffu, r0, s);
        r1 += __shfl_xor_sync(0xffffffffu, r1, s);
        r2 += __shfl_xor_sync(0xffffffffu, r2, s);
        r3 += __shfl_xor_sync(0xffffffffu, r3, s);
    }
    if (l == 0) {
        y[wrow + 0] = r0 + bias[wrow + 0];
        y[wrow + 1] = r1 + bias[wrow + 1];
        y[wrow + 2] = r2 + bias[wrow + 2];
        y[wrow + 3] = r3 + bias[wrow + 3];
    }
}

extern "C" void kernel_launch(void* const* d_in, const int* in_sizes, int n_in,
                              void* d_out, int out_size)
{
    const float* x    = (const float*)d_in[0];
    const int*   qw   = (const int*)d_in[1];
    const float* kv   = (const float*)d_in[2];
    const float* bias = (const float*)d_in[3];
    float*       y    = (float*)d_out;

    dim3 grid(OUT_F / RPB);   // 1792 blocks of 4 warps (4 rows per warp)
    dim3 block(128);
    q3_matvec_kernel<<<grid, block>>>(x, qw, kv, bias, y);
}

// round 12
// speedup vs baseline: 1.2872x; 1.0055x over previous
#include <cuda_runtime.h>
#include <cstdint>

#define OUT_F 28672
#define IN_F  8192
#define ROW_BYTES 16384            // int32-widened qweight row: 4096 * 4 B
#define RPB 8                      // rows per block (2 warps x 4 rows)
#define CHUNK_B 1024               // bytes per row per stage
#define NCHUNK (ROW_BYTES / CHUNK_B)   // 16
#define STAGE_B (RPB * CHUNK_B)        // 8 KB per stage

// qweight is int32 (harness-widened uint8): each element is a byte value
// 0..255 = two 4-bit codes (lo nibble -> even column, hi nibble -> odd).
//
// R11 structure (1 KB contiguous TMA chunks, parallel refill, 4 rows/warp)
// taken one step further down the proven convoy lever: 2-warp blocks at 12
// pipelines/SM (R10: 8w/3 -> 71.6% DRAM; R11: 4w/6 -> 79.0%). Barrier domain
// = 2 warps; 12 de-synchronized DRAM request generators per SM. In-flight,
// warps/SM, and L1 amortization all unchanged.

__device__ __forceinline__ uint32_t smem_u32(const void* p) {
    return (uint32_t)__cvta_generic_to_shared(p);
}
__device__ __forceinline__ void mbar_init(uint32_t mbar, uint32_t count) {
    asm volatile("mbarrier.init.shared.b64 [%0], %1;" :: "r"(mbar), "r"(count) : "memory");
}
__device__ __forceinline__ void mbar_expect_tx(uint32_t mbar, uint32_t bytes) {
    asm volatile("mbarrier.arrive.expect_tx.shared.b64 _, [%0], %1;"
                 :: "r"(mbar), "r"(bytes) : "memory");
}
__device__ __forceinline__ void bulk_g2s(uint32_t dst, const void* src,
                                         uint32_t bytes, uint32_t mbar) {
    asm volatile(
        "cp.async.bulk.shared::cluster.global.mbarrier::complete_tx::bytes "
        "[%0], [%1], %2, [%3];"
        :: "r"(dst), "l"(src), "r"(bytes), "r"(mbar) : "memory");
}
__device__ __forceinline__ void mbar_wait(uint32_t mbar, uint32_t parity) {
    uint32_t done;
    asm volatile(
        "{\n\t.reg .pred p;\n\t"
        "mbarrier.try_wait.parity.acquire.cta.shared::cta.b64 p, [%1], %2;\n\t"
        "selp.b32 %0, 1, 0, p;\n\t}"
        : "=r"(done) : "r"(mbar), "r"(parity) : "memory");
    if (!done) {
        asm volatile(
            "{\n\t.reg .pred P1;\n\t"
            "WL_%=:\n\t"
            "mbarrier.try_wait.parity.acquire.cta.shared::cta.b64 P1, [%0], %1, 0x989680;\n\t"
            "@P1 bra.uni WD_%=;\n\t"
            "bra.uni WL_%=;\n\t"
            "WD_%=:\n\t}"
            :: "r"(mbar), "r"(parity) : "memory");
    }
}

__global__ __launch_bounds__(64, 12)
void q3_matvec_kernel(const float* __restrict__ x,
                      const int* __restrict__ qw,
                      const float* __restrict__ kv,
                      const float* __restrict__ bias,
                      float* __restrict__ y)
{
    __shared__ alignas(128) uint8_t s_buf[2][STAGE_B];   // 2 x 8 KB
    __shared__ float s_lut[RPB * 16];                    // 8 row-LUTs (512 B)
    __shared__ alignas(8) uint64_t s_mbar[2];

    const int t = threadIdx.x;
    const int w = t >> 5;
    const int l = t & 31;
    const int rbase = blockIdx.x * RPB;
    const int wrow = rbase + (w << 2);      // this warp's 4 rows

    // Stage 128 LUT floats (2 per thread).
    s_lut[t]      = kv[rbase * 16 + t];
    s_lut[t + 64] = kv[rbase * 16 + t + 64];

    const uint32_t mb0 = smem_u32(&s_mbar[0]);
    const uint32_t mb1 = smem_u32(&s_mbar[1]);
    const uint32_t bu0 = smem_u32(&s_buf[0][0]);
    const uint32_t bu1 = smem_u32(&s_buf[1][0]);

    if (t == 0) { mbar_init(mb0, 1); mbar_init(mb1, 1); }
    __syncthreads();

    const char* gq = (const char*)qw + (size_t)rbase * ROW_BYTES;

    // Prologue: fill both stages (chunks 0 and 1), 8 parallel issuers.
    if (t == 0) { mbar_expect_tx(mb0, STAGE_B); mbar_expect_tx(mb1, STAGE_B); }
    if (t < RPB) {
        __syncwarp(0x000000ffu);
        const char* rowp = gq + (size_t)t * ROW_BYTES;
        bulk_g2s(bu0 + t * CHUNK_B, rowp,           CHUNK_B, mb0);
        bulk_g2s(bu1 + t * CHUNK_B, rowp + CHUNK_B, CHUNK_B, mb1);
    }

    const float* lut0 = s_lut + (w << 2) * 16;
    const float4* xp = reinterpret_cast<const float4*>(x);

    float a00 = 0.f, a01 = 0.f;
    float a10 = 0.f, a11 = 0.f;
    float a20 = 0.f, a21 = 0.f;
    float a30 = 0.f, a31 = 0.f;

    #pragma unroll 1
    for (int c = 0; c < NCHUNK; c++) {
        const int st = c & 1;
        const uint32_t mb = st ? mb1 : mb0;
        mbar_wait(mb, (c >> 1) & 1);

        const uint8_t* wbuf = s_buf[st] + ((w << 2) * CHUNK_B);

        // Two 512 B half-chunks per row; x window per half from L1.
        #pragma unroll
        for (int h = 0; h < 2; h++) {
            const float4 xa = xp[(c << 7) + (h << 6) + (l << 1)];
            const float4 xb = xp[(c << 7) + (h << 6) + (l << 1) + 1];
            const uint8_t* buf = wbuf + (h << 9) + (l << 4);

            const uint4 q0 = *reinterpret_cast<const uint4*>(buf);
            const uint4 q1 = *reinterpret_cast<const uint4*>(buf + CHUNK_B);
            const uint4 q2 = *reinterpret_cast<const uint4*>(buf + 2 * CHUNK_B);
            const uint4 q3 = *reinterpret_cast<const uint4*>(buf + 3 * CHUNK_B);

            // v <= 255 so (v >> 4) is already a clean code (no mask).
            #define DO_ROW(Q, LUT, A0, A1)                        \
                A0 = fmaf((LUT)[(Q).x & 15u], xa.x, A0);          \
                A1 = fmaf((LUT)[(Q).x >> 4],  xa.y, A1);          \
                A0 = fmaf((LUT)[(Q).y & 15u], xa.z, A0);          \
                A1 = fmaf((LUT)[(Q).y >> 4],  xa.w, A1);          \
                A0 = fmaf((LUT)[(Q).z & 15u], xb.x, A0);          \
                A1 = fmaf((LUT)[(Q).z >> 4],  xb.y, A1);          \
                A0 = fmaf((LUT)[(Q).w & 15u], xb.z, A0);          \
                A1 = fmaf((LUT)[(Q).w >> 4],  xb.w, A1);

            DO_ROW(q0, lut0,      a00, a01)
            DO_ROW(q1, lut0 + 16, a10, a11)
            DO_ROW(q2, lut0 + 32, a20, a21)
            DO_ROW(q3, lut0 + 48, a30, a31)
            #undef DO_ROW
        }

        __syncthreads();   // stage st fully consumed (2-warp barrier)

        if (c + 2 < NCHUNK) {
            if (t == 0) mbar_expect_tx(mb, STAGE_B);
            if (t < RPB) {
                __syncwarp(0x000000ffu);
                const uint32_t bu = st ? bu1 : bu0;
                bulk_g2s(bu + t * CHUNK_B,
                         gq + (size_t)t * ROW_BYTES + (size_t)(c + 2) * CHUNK_B,
                         CHUNK_B, mb);
            }
        }
    }

    // Four reductions per warp, once.
    float r0 = a00 + a01;
    float r1 = a10 + a11;
    float r2 = a20 + a21;
    float r3 = a30 + a31;
    #pragma unroll
    for (int s = 16; s > 0; s >>= 1) {
        r0 += __shfl_xor_sync(0xffffffffu, r0, s);
        r1 += __shfl_xor_sync(0xffffffffu, r1, s);
        r2 += __shfl_xor_sync(0xffffffffu, r2, s);
        r3 += __shfl_xor_sync(0xffffffffu, r3, s);
    }
    if (l == 0) {
        y[wrow + 0] = r0 + bias[wrow + 0];
        y[wrow + 1] = r1 + bias[wrow + 1];
        y[wrow + 2] = r2 + bias[wrow + 2];
        y[wrow + 3] = r3 + bias[wrow + 3];
    }
}

extern "C" void kernel_launch(void* const* d_in, const int* in_sizes, int n_in,
                              void* d_out, int out_size)
{
    const float* x    = (const float*)d_in[0];
    const int*   qw   = (const int*)d_in[1];
    const float* kv   = (const float*)d_in[2];
    const float* bias = (const float*)d_in[3];
    float*       y    = (float*)d_out;

    dim3 grid(OUT_F / RPB);   // 3584 blocks of 2 warps (4 rows per warp)
    dim3 block(64);
    q3_matvec_kernel<<<grid, block>>>(x, qw, kv, bias, y);
}